// round 2
// baseline (speedup 1.0000x reference)
#include <cuda_runtime.h>
#include <cuda_bf16.h>
#include <mma.h>

using namespace nvcuda;

#define B_ 16
#define S_ 2048
#define E_ 768
#define H_ 96
#define M_ (B_*S_)

// Scratch for projected q,k,v (static device arrays: allocation-rule safe)
__device__ float g_q[M_*H_];
__device__ float g_k[M_*H_];
__device__ float g_v[M_*H_];

// ----------------------------- QKV projection -----------------------------
// C[32768,96] = X[32768,768] @ W[768,96], tf32 wmma m16n16k8.
#define PBM 64
#define PBK 32
#define ALD (PBK+4)   // 36
#define BLD (H_+8)    // 104

__global__ __launch_bounds__(128) void qkv_kernel(
    const float* __restrict__ X,
    const float* __restrict__ Wq,
    const float* __restrict__ Wk,
    const float* __restrict__ Wv)
{
    __shared__ float As[PBM][ALD];
    __shared__ float Bs[PBK][BLD];

    const int tid  = threadIdx.x;
    const int warp = tid >> 5;
    const int row0 = blockIdx.x * PBM;

    const float* W;
    float* Out;
    if (blockIdx.y == 0)      { W = Wq; Out = g_q; }
    else if (blockIdx.y == 1) { W = Wk; Out = g_k; }
    else                      { W = Wv; Out = g_v; }

    wmma::fragment<wmma::accumulator, 16,16,8, float> c[6];
    #pragma unroll
    for (int j = 0; j < 6; j++) wmma::fill_fragment(c[j], 0.0f);

    for (int kt = 0; kt < E_/PBK; kt++) {
        // Load A tile 64x32 (512 float4, 4 per thread), convert to tf32
        #pragma unroll
        for (int i = 0; i < 4; i++) {
            int idx = tid + i*128;
            int r = idx >> 3, c4 = idx & 7;
            float4 v = *reinterpret_cast<const float4*>(
                &X[(size_t)(row0 + r)*E_ + kt*PBK + c4*4]);
            float* d = &As[r][c4*4];
            d[0] = wmma::__float_to_tf32(v.x);
            d[1] = wmma::__float_to_tf32(v.y);
            d[2] = wmma::__float_to_tf32(v.z);
            d[3] = wmma::__float_to_tf32(v.w);
        }
        // Load B tile 32x96 (768 float4, 6 per thread)
        #pragma unroll
        for (int i = 0; i < 6; i++) {
            int idx = tid + i*128;
            int r = idx / 24, c4 = idx - r*24;
            float4 v = *reinterpret_cast<const float4*>(
                &W[(size_t)(kt*PBK + r)*H_ + c4*4]);
            float* d = &Bs[r][c4*4];
            d[0] = wmma::__float_to_tf32(v.x);
            d[1] = wmma::__float_to_tf32(v.y);
            d[2] = wmma::__float_to_tf32(v.z);
            d[3] = wmma::__float_to_tf32(v.w);
        }
        __syncthreads();

        #pragma unroll
        for (int ks = 0; ks < 4; ks++) {
            wmma::fragment<wmma::matrix_a, 16,16,8, wmma::precision::tf32, wmma::row_major> a;
            wmma::load_matrix_sync(a, &As[warp*16][ks*8], ALD);
            #pragma unroll
            for (int j = 0; j < 6; j++) {
                wmma::fragment<wmma::matrix_b, 16,16,8, wmma::precision::tf32, wmma::row_major> b;
                wmma::load_matrix_sync(b, &Bs[ks*8][j*16], BLD);
                wmma::mma_sync(c[j], a, b, c[j]);
            }
        }
        __syncthreads();
    }

    #pragma unroll
    for (int j = 0; j < 6; j++)
        wmma::store_matrix_sync(&Out[(size_t)(row0 + warp*16)*H_ + j*16], c[j],
                                H_, wmma::mem_row_major);
}

// ----------------------------- Attention -----------------------------
// Two-pass tiled causal attention. 64-row q-tiles, 64-col kv-tiles.
#define QLD 104   // ld for 64x96 tiles (Q, K, V) in smem
#define SLD 72    // ld for 64x64 score tile

// Total dynamic smem (floats): 3*64*QLD + 64*SLD + 128
#define ATTN_SMEM_FLOATS (3*64*QLD + 64*SLD + 128)
#define ATTN_SMEM_BYTES  (ATTN_SMEM_FLOATS * 4)

__device__ __forceinline__ void load_tile96(const float* __restrict__ g, int grow0,
                                            float* __restrict__ dst, int tid)
{
    #pragma unroll
    for (int i = 0; i < 12; i++) {
        int idx = tid + i*128;            // 1536 float4 total
        int r = idx / 24, c4 = idx - r*24;
        float4 v = *reinterpret_cast<const float4*>(
            &g[(size_t)(grow0 + r)*H_ + c4*4]);
        float* d = &dst[r*QLD + c4*4];
        d[0] = wmma::__float_to_tf32(v.x);
        d[1] = wmma::__float_to_tf32(v.y);
        d[2] = wmma::__float_to_tf32(v.z);
        d[3] = wmma::__float_to_tf32(v.w);
    }
}

// S[64,64] = Q[64,96] @ K^T  (K stored row-major [token, h] -> col_major B frag)
__device__ __forceinline__ void s_gemm(const float* __restrict__ Qs,
                                       const float* __restrict__ Ks,
                                       float* __restrict__ Ss, int warp)
{
    wmma::fragment<wmma::accumulator, 16,16,8, float> c[4];
    #pragma unroll
    for (int j = 0; j < 4; j++) wmma::fill_fragment(c[j], 0.0f);
    #pragma unroll
    for (int ks = 0; ks < 12; ks++) {
        wmma::fragment<wmma::matrix_a, 16,16,8, wmma::precision::tf32, wmma::row_major> a;
        wmma::load_matrix_sync(a, &Qs[warp*16*QLD + ks*8], QLD);
        #pragma unroll
        for (int j = 0; j < 4; j++) {
            wmma::fragment<wmma::matrix_b, 16,16,8, wmma::precision::tf32, wmma::col_major> bf;
            wmma::load_matrix_sync(bf, &Ks[(j*16)*QLD + ks*8], QLD);
            wmma::mma_sync(c[j], a, bf, c[j]);
        }
    }
    #pragma unroll
    for (int j = 0; j < 4; j++)
        wmma::store_matrix_sync(&Ss[warp*16*SLD + j*16], c[j], SLD, wmma::mem_row_major);
}

__global__ __launch_bounds__(128) void attn_kernel(float* __restrict__ out)
{
    extern __shared__ float smem[];
    float* Qs   = smem;
    float* Ks   = Qs + 64*QLD;
    float* Vs   = Ks + 64*QLD;
    float* Ss   = Vs + 64*QLD;
    float* mrow = Ss + 64*SLD;
    float* lrow = mrow + 64;

    const int tid  = threadIdx.x;
    const int warp = tid >> 5;
    const int qt   = blockIdx.x;
    const int b    = blockIdx.y;
    const int rq   = b*S_ + qt*64;        // global row base in [M, H]
    const float SCALE = 0.1020620726159658f;  // 96^-0.5

    load_tile96(g_q, rq, Qs, tid);
    if (tid < 64) { mrow[tid] = -1e30f; lrow[tid] = 0.0f; }
    __syncthreads();

    const int row  = tid >> 1;     // 0..63
    const int half = tid & 1;      // each pair of lanes splits a row's 64 cols
    const int rg   = qt*64 + row;  // global query index within batch

    // ---------------- Pass 1: row max & denominator ----------------
    for (int kt = 0; kt <= qt; kt++) {
        load_tile96(g_k, b*S_ + kt*64, Ks, tid);
        __syncthreads();
        s_gemm(Qs, Ks, Ss, warp);
        __syncthreads();

        {
            const int cg0 = kt*64 + half*32;
            float mold = mrow[row];
            float pm = -1e30f;
            #pragma unroll 8
            for (int c = 0; c < 32; c++) {
                float s = Ss[row*SLD + half*32 + c] * SCALE;
                if (cg0 + c > rg) s = -1e30f;
                pm = fmaxf(pm, s);
            }
            float om = __shfl_xor_sync(0xffffffffu, pm, 1);
            float newm = fmaxf(mold, fmaxf(pm, om));
            float ps = 0.0f;
            #pragma unroll 8
            for (int c = 0; c < 32; c++) {
                float s = Ss[row*SLD + half*32 + c] * SCALE;
                if (cg0 + c > rg) continue;
                ps += __expf(s - newm);
            }
            float os = __shfl_xor_sync(0xffffffffu, ps, 1);
            if (half == 0) {
                lrow[row] = lrow[row] * __expf(mold - newm) + ps + os;
                mrow[row] = newm;
            }
        }
        __syncthreads();
    }

    // ---------------- Pass 2: recompute S, form P, accumulate O = P@V ----
    wmma::fragment<wmma::accumulator, 16,16,8, float> o[6];
    #pragma unroll
    for (int j = 0; j < 6; j++) wmma::fill_fragment(o[j], 0.0f);

    for (int kt = 0; kt <= qt; kt++) {
        load_tile96(g_k, b*S_ + kt*64, Ks, tid);
        __syncthreads();
        s_gemm(Qs, Ks, Ss, warp);
        __syncthreads();

        {
            const int cg0 = kt*64 + half*32;
            float m = mrow[row];
            float invl = 1.0f / lrow[row];
            #pragma unroll 8
            for (int c = 0; c < 32; c++) {
                float s = Ss[row*SLD + half*32 + c] * SCALE;
                float p = (cg0 + c > rg) ? 0.0f : __expf(s - m) * invl;
                Ss[row*SLD + half*32 + c] = wmma::__float_to_tf32(p);
            }
        }
        load_tile96(g_v, b*S_ + kt*64, Vs, tid);
        __syncthreads();

        #pragma unroll
        for (int ks = 0; ks < 8; ks++) {
            wmma::fragment<wmma::matrix_a, 16,16,8, wmma::precision::tf32, wmma::row_major> a;
            wmma::load_matrix_sync(a, &Ss[warp*16*SLD + ks*8], SLD);
            #pragma unroll
            for (int j = 0; j < 6; j++) {
                wmma::fragment<wmma::matrix_b, 16,16,8, wmma::precision::tf32, wmma::row_major> bv;
                wmma::load_matrix_sync(bv, &Vs[(ks*8)*QLD + j*16], QLD);
                wmma::mma_sync(o[j], a, bv, o[j]);
            }
        }
        __syncthreads();
    }

    #pragma unroll
    for (int j = 0; j < 6; j++)
        wmma::store_matrix_sync(&out[(size_t)(rq + warp*16)*H_ + j*16], o[j],
                                H_, wmma::mem_row_major);
}

// ----------------------------- Launch -----------------------------
extern "C" void kernel_launch(void* const* d_in, const int* in_sizes, int n_in,
                              void* d_out, int out_size)
{
    const float* x  = (const float*)d_in[0];
    const float* Wq = (const float*)d_in[1];
    const float* Wk = (const float*)d_in[2];
    const float* Wv = (const float*)d_in[3];
    float* out = (float*)d_out;

    cudaFuncSetAttribute(attn_kernel, cudaFuncAttributeMaxDynamicSharedMemorySize,
                         ATTN_SMEM_BYTES);

    dim3 g1(M_/PBM, 3);
    qkv_kernel<<<g1, 128>>>(x, Wq, Wk, Wv);

    dim3 g2(S_/64, B_);
    attn_kernel<<<g2, 128, ATTN_SMEM_BYTES>>>(out);
}

// round 4
// speedup vs baseline: 1.3294x; 1.3294x over previous
#include <cuda_runtime.h>
#include <cuda_bf16.h>
#include <mma.h>

using namespace nvcuda;

#define B_ 16
#define S_ 2048
#define E_ 768
#define H_ 96
#define M_ (B_*S_)

// Scratch for projected q,k,v (static device arrays: allocation-rule safe)
__device__ float g_q[M_*H_];
__device__ float g_k[M_*H_];
__device__ float g_v[M_*H_];

// ----------------------------- QKV projection -----------------------------
// C[32768,96] = X[32768,768] @ W[768,96], tf32 wmma m16n16k8.
// 256 threads, 8 warps. Block tile 256 rows; warp tile 32x96 (b-frag reuse 2x).
#define PBM 256
#define PBK 32
#define ALD (PBK+4)   // 36
#define BLD (H_+8)    // 104
#define QKV_SMEM_FLOATS (PBM*ALD + PBK*BLD)
#define QKV_SMEM_BYTES  (QKV_SMEM_FLOATS*4)

__global__ __launch_bounds__(256) void qkv_kernel(
    const float* __restrict__ X,
    const float* __restrict__ Wq,
    const float* __restrict__ Wk,
    const float* __restrict__ Wv)
{
    extern __shared__ float qsmem[];
    float* As = qsmem;              // [PBM][ALD]
    float* Bs = qsmem + PBM*ALD;    // [PBK][BLD]

    const int tid  = threadIdx.x;
    const int warp = tid >> 5;
    const int row0 = blockIdx.x * PBM;

    const float* W;
    float* Out;
    if (blockIdx.y == 0)      { W = Wq; Out = g_q; }
    else if (blockIdx.y == 1) { W = Wk; Out = g_k; }
    else                      { W = Wv; Out = g_v; }

    wmma::fragment<wmma::accumulator, 16,16,8, float> c[6][2];
    #pragma unroll
    for (int j = 0; j < 6; j++) {
        wmma::fill_fragment(c[j][0], 0.0f);
        wmma::fill_fragment(c[j][1], 0.0f);
    }

    for (int kt = 0; kt < E_/PBK; kt++) {
        // A tile 256x32 = 2048 float4, 8 per thread
        #pragma unroll
        for (int i = 0; i < 8; i++) {
            int idx = tid + i*256;
            int r = idx >> 3, c4 = idx & 7;
            float4 v = *reinterpret_cast<const float4*>(
                &X[(size_t)(row0 + r)*E_ + kt*PBK + c4*4]);
            float* d = &As[r*ALD + c4*4];
            d[0] = wmma::__float_to_tf32(v.x);
            d[1] = wmma::__float_to_tf32(v.y);
            d[2] = wmma::__float_to_tf32(v.z);
            d[3] = wmma::__float_to_tf32(v.w);
        }
        // B tile 32x96 = 768 float4, 3 per thread
        #pragma unroll
        for (int i = 0; i < 3; i++) {
            int idx = tid + i*256;
            int r = idx / 24, c4 = idx - r*24;
            float4 v = *reinterpret_cast<const float4*>(
                &W[(size_t)(kt*PBK + r)*H_ + c4*4]);
            float* d = &Bs[r*BLD + c4*4];
            d[0] = wmma::__float_to_tf32(v.x);
            d[1] = wmma::__float_to_tf32(v.y);
            d[2] = wmma::__float_to_tf32(v.z);
            d[3] = wmma::__float_to_tf32(v.w);
        }
        __syncthreads();

        #pragma unroll
        for (int ks = 0; ks < 4; ks++) {
            wmma::fragment<wmma::matrix_a, 16,16,8, wmma::precision::tf32, wmma::row_major> a0, a1;
            wmma::load_matrix_sync(a0, &As[(warp*32)*ALD + ks*8], ALD);
            wmma::load_matrix_sync(a1, &As[(warp*32+16)*ALD + ks*8], ALD);
            #pragma unroll
            for (int j = 0; j < 6; j++) {
                wmma::fragment<wmma::matrix_b, 16,16,8, wmma::precision::tf32, wmma::row_major> b;
                wmma::load_matrix_sync(b, &Bs[(ks*8)*BLD + j*16], BLD);
                wmma::mma_sync(c[j][0], a0, b, c[j][0]);
                wmma::mma_sync(c[j][1], a1, b, c[j][1]);
            }
        }
        __syncthreads();
    }

    #pragma unroll
    for (int j = 0; j < 6; j++) {
        wmma::store_matrix_sync(&Out[(size_t)(row0 + warp*32)*H_ + j*16], c[j][0],
                                H_, wmma::mem_row_major);
        wmma::store_matrix_sync(&Out[(size_t)(row0 + warp*32 + 16)*H_ + j*16], c[j][1],
                                H_, wmma::mem_row_major);
    }
}

// ----------------------------- Attention -----------------------------
// ONE-PASS flash attention. 64-row q-tiles, 64-col kv-tiles, 256 threads (8 warps).
// Warps: wr = warp&3 (row group of 16), wc = warp>>2 (col group).
// O accumulator in registers: thread (row=tid>>2, q4=tid&3) owns cols [q4*24, q4*24+24).
// PV partial goes through smem (reusing the K buffer) to apply the online rescale.
#define QLD 104   // ld for 64x96 tiles (Q, K, V, PV-tmp) in smem
#define SLD 72    // ld for 64x64 score tile

#define ATTN_SMEM_FLOATS (3*64*QLD + 64*SLD + 128)
#define ATTN_SMEM_BYTES  (ATTN_SMEM_FLOATS * 4)

__device__ __forceinline__ void load_tile96_256(const float* __restrict__ g, int grow0,
                                                float* __restrict__ dst, int tid)
{
    #pragma unroll
    for (int i = 0; i < 6; i++) {
        int idx = tid + i*256;            // 1536 float4 total (64 rows x 24 f4)
        int r = idx / 24, c4 = idx - r*24;
        float4 v = *reinterpret_cast<const float4*>(
            &g[(size_t)(grow0 + r)*H_ + c4*4]);
        float* d = &dst[r*QLD + c4*4];
        d[0] = wmma::__float_to_tf32(v.x);
        d[1] = wmma::__float_to_tf32(v.y);
        d[2] = wmma::__float_to_tf32(v.z);
        d[3] = wmma::__float_to_tf32(v.w);
    }
}

__global__ __launch_bounds__(256, 2) void attn_kernel(float* __restrict__ out)
{
    extern __shared__ float smem[];
    float* Qs   = smem;
    float* Ks   = Qs + 64*QLD;   // doubles as PV-partial buffer after s_gemm
    float* Vs   = Ks + 64*QLD;
    float* Ss   = Vs + 64*QLD;
    float* mrow = Ss + 64*SLD;
    float* lrow = mrow + 64;

    const int tid  = threadIdx.x;
    const int warp = tid >> 5;
    const int wr   = warp & 3;
    const int wc   = warp >> 2;
    const int qt   = blockIdx.x;
    const int b    = blockIdx.y;
    const int rq   = b*S_ + qt*64;
    const float SCALE = 0.1020620726159658f;  // 96^-0.5

    const int row = tid >> 2;     // 0..63
    const int q4  = tid & 3;      // 4 lanes per row, 16 score cols / 24 O cols each
    const int rg  = qt*64 + row;  // global query index within batch

    load_tile96_256(g_q, rq, Qs, tid);
    if (tid < 64) { mrow[tid] = -1e30f; lrow[tid] = 0.0f; }

    float O[24];
    #pragma unroll
    for (int i = 0; i < 24; i++) O[i] = 0.0f;
    __syncthreads();

    for (int kt = 0; kt <= qt; kt++) {
        load_tile96_256(g_k, b*S_ + kt*64, Ks, tid);
        load_tile96_256(g_v, b*S_ + kt*64, Vs, tid);
        __syncthreads();

        // ---- S = Q @ K^T : warp computes rows wr*16, cols wc*32 ----
        {
            wmma::fragment<wmma::accumulator, 16,16,8, float> c0, c1;
            wmma::fill_fragment(c0, 0.0f);
            wmma::fill_fragment(c1, 0.0f);
            #pragma unroll
            for (int ks = 0; ks < 12; ks++) {
                wmma::fragment<wmma::matrix_a, 16,16,8, wmma::precision::tf32, wmma::row_major> a;
                wmma::load_matrix_sync(a, &Qs[(wr*16)*QLD + ks*8], QLD);
                wmma::fragment<wmma::matrix_b, 16,16,8, wmma::precision::tf32, wmma::col_major> b0, b1;
                wmma::load_matrix_sync(b0, &Ks[(wc*32)*QLD + ks*8], QLD);
                wmma::load_matrix_sync(b1, &Ks[(wc*32+16)*QLD + ks*8], QLD);
                wmma::mma_sync(c0, a, b0, c0);
                wmma::mma_sync(c1, a, b1, c1);
            }
            wmma::store_matrix_sync(&Ss[(wr*16)*SLD + wc*32],      c0, SLD, wmma::mem_row_major);
            wmma::store_matrix_sync(&Ss[(wr*16)*SLD + wc*32 + 16], c1, SLD, wmma::mem_row_major);
        }
        __syncthreads();

        // ---- online softmax: each thread handles 16 cols of its row ----
        float f;   // rescale factor, identical across the 4 lanes of a row
        {
            const float mold = mrow[row];
            const int   cg0  = kt*64 + q4*16;
            float pm = -1e30f;
            #pragma unroll
            for (int i = 0; i < 16; i++) {
                float s = Ss[row*SLD + q4*16 + i] * SCALE;
                if (cg0 + i > rg) s = -1e30f;
                pm = fmaxf(pm, s);
            }
            pm = fmaxf(pm, __shfl_xor_sync(0xffffffffu, pm, 1));
            pm = fmaxf(pm, __shfl_xor_sync(0xffffffffu, pm, 2));
            const float newm = fmaxf(mold, pm);
            float ps = 0.0f;
            #pragma unroll
            for (int i = 0; i < 16; i++) {
                float s = Ss[row*SLD + q4*16 + i] * SCALE;
                float p = (cg0 + i > rg) ? 0.0f : __expf(s - newm);
                ps += p;
                Ss[row*SLD + q4*16 + i] = wmma::__float_to_tf32(p);
            }
            ps += __shfl_xor_sync(0xffffffffu, ps, 1);
            ps += __shfl_xor_sync(0xffffffffu, ps, 2);
            f = __expf(mold - newm);
            if (q4 == 0) { mrow[row] = newm; lrow[row] = lrow[row]*f + ps; }
        }
        __syncthreads();

        // ---- PV = P @ V : warp computes rows wr*16, cols wc*48 -> Ks (as tmp) ----
        {
            wmma::fragment<wmma::accumulator, 16,16,8, float> d[3];
            #pragma unroll
            for (int j = 0; j < 3; j++) wmma::fill_fragment(d[j], 0.0f);
            #pragma unroll
            for (int ks = 0; ks < 8; ks++) {
                wmma::fragment<wmma::matrix_a, 16,16,8, wmma::precision::tf32, wmma::row_major> a;
                wmma::load_matrix_sync(a, &Ss[(wr*16)*SLD + ks*8], SLD);
                #pragma unroll
                for (int j = 0; j < 3; j++) {
                    wmma::fragment<wmma::matrix_b, 16,16,8, wmma::precision::tf32, wmma::row_major> bv;
                    wmma::load_matrix_sync(bv, &Vs[(ks*8)*QLD + wc*48 + j*16], QLD);
                    wmma::mma_sync(d[j], a, bv, d[j]);
                }
            }
            #pragma unroll
            for (int j = 0; j < 3; j++)
                wmma::store_matrix_sync(&Ks[(wr*16)*QLD + wc*48 + j*16], d[j],
                                        QLD, wmma::mem_row_major);
        }
        __syncthreads();

        // ---- O = O * f + PV_partial ----
        #pragma unroll
        for (int i = 0; i < 24; i++)
            O[i] = O[i]*f + Ks[row*QLD + q4*24 + i];
        __syncthreads();   // protect Ks/Vs/Ss before next iteration overwrites
    }

    const float invl = 1.0f / lrow[row];
    #pragma unroll
    for (int i = 0; i < 24; i += 4) {
        float4 v;
        v.x = O[i+0]*invl; v.y = O[i+1]*invl;
        v.z = O[i+2]*invl; v.w = O[i+3]*invl;
        *reinterpret_cast<float4*>(&out[(size_t)(rq + row)*H_ + q4*24 + i]) = v;
    }
}

// ----------------------------- Launch -----------------------------
extern "C" void kernel_launch(void* const* d_in, const int* in_sizes, int n_in,
                              void* d_out, int out_size)
{
    const float* x  = (const float*)d_in[0];
    const float* Wq = (const float*)d_in[1];
    const float* Wk = (const float*)d_in[2];
    const float* Wv = (const float*)d_in[3];
    float* out = (float*)d_out;

    cudaFuncSetAttribute(qkv_kernel, cudaFuncAttributeMaxDynamicSharedMemorySize,
                         QKV_SMEM_BYTES);
    cudaFuncSetAttribute(attn_kernel, cudaFuncAttributeMaxDynamicSharedMemorySize,
                         ATTN_SMEM_BYTES);

    dim3 g1(M_/PBM, 3);
    qkv_kernel<<<g1, 256, QKV_SMEM_BYTES>>>(x, Wq, Wk, Wv);

    dim3 g2(S_/64, B_);
    attn_kernel<<<g2, 256, ATTN_SMEM_BYTES>>>(out);
}

// round 6
// speedup vs baseline: 2.8567x; 2.1488x over previous
#include <cuda_runtime.h>
#include <cuda_bf16.h>
#include <cstdint>

#define B_ 16
#define S_ 2048
#define E_ 768
#define H_ 96
#define M_ (B_*S_)

// Scratch for projected q,k,v
__device__ float g_q[M_*H_];
__device__ float g_k[M_*H_];
__device__ float g_v[M_*H_];

// round-to-nearest fp32 -> tf32 (keeps bit pattern in a float)
__device__ __forceinline__ float to_tf32(float x)
{
    asm("cvt.rna.tf32.f32 %0, %1;" : "=f"(x) : "f"(x));
    return x;
}

// raw tf32 mma m16n8k8: D = A*B + D (A row-major 16x8, B col-major 8x8)
__device__ __forceinline__ void mma8(float c[4],
                                     uint32_t a0, uint32_t a1, uint32_t a2, uint32_t a3,
                                     uint32_t b0, uint32_t b1)
{
    asm volatile(
        "mma.sync.aligned.m16n8k8.row.col.f32.tf32.tf32.f32 "
        "{%0,%1,%2,%3}, {%4,%5,%6,%7}, {%8,%9}, {%0,%1,%2,%3};\n"
        : "+f"(c[0]), "+f"(c[1]), "+f"(c[2]), "+f"(c[3])
        : "r"(a0), "r"(a1), "r"(a2), "r"(a3), "r"(b0), "r"(b1));
}

// ----------------------------- QKV projection -----------------------------
// C[32768,96] = X @ W. 128 threads = 4 warps, each warp 32 rows x 96 cols.
#define XLD 36
#define WLD 104
#define QKV_SMEM_BYTES ((128*XLD + 32*WLD)*4)

__global__ __launch_bounds__(128) void qkv_kernel(
    const float* __restrict__ X,
    const float* __restrict__ Wq,
    const float* __restrict__ Wk,
    const float* __restrict__ Wv)
{
    extern __shared__ float qs[];
    float* Xs = qs;             // [128][XLD]
    float* Ws = qs + 128*XLD;   // [32][WLD]

    const int tid  = threadIdx.x;
    const int w    = tid >> 5;
    const int lane = tid & 31;
    const int g    = lane >> 2;
    const int t    = lane & 3;
    const int row0 = blockIdx.x * 128;

    const float* W;
    float* Out;
    if (blockIdx.y == 0)      { W = Wq; Out = g_q; }
    else if (blockIdx.y == 1) { W = Wk; Out = g_k; }
    else                      { W = Wv; Out = g_v; }

    float o[2][12][4];
    #pragma unroll
    for (int r = 0; r < 2; r++)
        #pragma unroll
        for (int n = 0; n < 12; n++)
            o[r][n][0] = o[r][n][1] = o[r][n][2] = o[r][n][3] = 0.0f;

    for (int kt = 0; kt < E_/32; kt++) {
        // X tile 128x32 = 1024 float4, 8 per thread
        #pragma unroll
        for (int i = 0; i < 8; i++) {
            int idx = tid + i*128;
            int r = idx >> 3, c4 = idx & 7;
            float4 v = *reinterpret_cast<const float4*>(
                &X[(size_t)(row0 + r)*E_ + kt*32 + c4*4]);
            float* d = &Xs[r*XLD + c4*4];
            d[0]=to_tf32(v.x); d[1]=to_tf32(v.y); d[2]=to_tf32(v.z); d[3]=to_tf32(v.w);
        }
        // W tile 32x96 = 768 float4, 6 per thread
        #pragma unroll
        for (int i = 0; i < 6; i++) {
            int idx = tid + i*128;
            int r = idx / 24, c4 = idx - r*24;
            float4 v = *reinterpret_cast<const float4*>(
                &W[(size_t)(kt*32 + r)*H_ + c4*4]);
            float* d = &Ws[r*WLD + c4*4];
            d[0]=to_tf32(v.x); d[1]=to_tf32(v.y); d[2]=to_tf32(v.z); d[3]=to_tf32(v.w);
        }
        __syncthreads();

        #pragma unroll
        for (int kc = 0; kc < 4; kc++) {
            uint32_t a[2][4];
            #pragma unroll
            for (int rt = 0; rt < 2; rt++) {
                int rr = w*32 + rt*16 + g;
                a[rt][0] = __float_as_uint(Xs[rr*XLD + kc*8 + t]);
                a[rt][1] = __float_as_uint(Xs[(rr+8)*XLD + kc*8 + t]);
                a[rt][2] = __float_as_uint(Xs[rr*XLD + kc*8 + t + 4]);
                a[rt][3] = __float_as_uint(Xs[(rr+8)*XLD + kc*8 + t + 4]);
            }
            #pragma unroll
            for (int n = 0; n < 12; n++) {
                uint32_t b0 = __float_as_uint(Ws[(kc*8 + t)*WLD + n*8 + g]);
                uint32_t b1 = __float_as_uint(Ws[(kc*8 + t + 4)*WLD + n*8 + g]);
                mma8(o[0][n], a[0][0],a[0][1],a[0][2],a[0][3], b0,b1);
                mma8(o[1][n], a[1][0],a[1][1],a[1][2],a[1][3], b0,b1);
            }
        }
        __syncthreads();
    }

    #pragma unroll
    for (int rt = 0; rt < 2; rt++) {
        int rr = row0 + w*32 + rt*16 + g;
        #pragma unroll
        for (int n = 0; n < 12; n++) {
            float2 lo = make_float2(o[rt][n][0], o[rt][n][1]);
            float2 hi = make_float2(o[rt][n][2], o[rt][n][3]);
            *reinterpret_cast<float2*>(&Out[(size_t)rr*H_ + n*8 + 2*t]) = lo;
            *reinterpret_cast<float2*>(&Out[(size_t)(rr+8)*H_ + n*8 + 2*t]) = hi;
        }
    }
}

// ----------------------------- Attention -----------------------------
// One-pass flash attention, raw mma. 128-row q-tiles (8 warps x 16 rows),
// 64-col kv-tiles. S in accum regs; P->A via shfl; O in accum regs.
#define LD 104
#define ATTN_SMEM_BYTES (2*64*LD*4)   // Ks + Vs; Q staging overlays both

__global__ __launch_bounds__(256) void attn_kernel(float* __restrict__ out)
{
    extern __shared__ float smem[];
    float* Ks     = smem;            // [64][LD]
    float* Vs     = smem + 64*LD;    // [64][LD]
    float* Qstage = smem;            // [128][LD] (overlay, pre-loop only)

    const int tid  = threadIdx.x;
    const int w    = tid >> 5;
    const int lane = tid & 31;
    const int g    = lane >> 2;
    const int t    = lane & 3;
    const int qt   = (S_/128 - 1) - blockIdx.x;   // big CTAs first
    const int b    = blockIdx.y;
    const int rq0  = b*S_ + qt*128;
    const float SCALE = 0.1020620726159658f;      // 96^-0.5

    // Stage Q (scaled, tf32-rounded) to smem, then preload A fragments
    #pragma unroll
    for (int i = 0; i < 12; i++) {
        int idx = tid + i*256;          // 128 rows x 24 f4 = 3072
        int r = idx / 24, c4 = idx - r*24;
        float4 v = *reinterpret_cast<const float4*>(
            &g_q[(size_t)(rq0 + r)*H_ + c4*4]);
        float* d = &Qstage[r*LD + c4*4];
        d[0]=to_tf32(v.x*SCALE); d[1]=to_tf32(v.y*SCALE);
        d[2]=to_tf32(v.z*SCALE); d[3]=to_tf32(v.w*SCALE);
    }
    __syncthreads();

    uint32_t qa[12][4];
    {
        const int qr = w*16 + g;
        #pragma unroll
        for (int kc = 0; kc < 12; kc++) {
            qa[kc][0] = __float_as_uint(Qstage[qr*LD + kc*8 + t]);
            qa[kc][1] = __float_as_uint(Qstage[(qr+8)*LD + kc*8 + t]);
            qa[kc][2] = __float_as_uint(Qstage[qr*LD + kc*8 + t + 4]);
            qa[kc][3] = __float_as_uint(Qstage[(qr+8)*LD + kc*8 + t + 4]);
        }
    }
    __syncthreads();

    float o[12][4];
    #pragma unroll
    for (int n = 0; n < 12; n++)
        o[n][0] = o[n][1] = o[n][2] = o[n][3] = 0.0f;

    float m_lo = -1e30f, m_hi = -1e30f, l_lo = 0.0f, l_hi = 0.0f;
    const int rlo = qt*128 + w*16 + g;   // absolute query row (lo)
    const int rhi = rlo + 8;
    const int nkt = 2*qt + 2;

    for (int kt = 0; kt < nkt; kt++) {
        // Load K,V tiles (64x96 each), tf32-rounded
        #pragma unroll
        for (int i = 0; i < 6; i++) {
            int idx = tid + i*256;       // 64 rows x 24 f4 = 1536
            int r = idx / 24, c4 = idx - r*24;
            size_t gb = (size_t)(b*S_ + kt*64 + r)*H_ + c4*4;
            float4 vk = *reinterpret_cast<const float4*>(&g_k[gb]);
            float4 vv = *reinterpret_cast<const float4*>(&g_v[gb]);
            float* dk = &Ks[r*LD + c4*4];
            float* dv = &Vs[r*LD + c4*4];
            dk[0]=to_tf32(vk.x); dk[1]=to_tf32(vk.y); dk[2]=to_tf32(vk.z); dk[3]=to_tf32(vk.w);
            dv[0]=to_tf32(vv.x); dv[1]=to_tf32(vv.y); dv[2]=to_tf32(vv.z); dv[3]=to_tf32(vv.w);
        }
        __syncthreads();

        // ---- S = Qscaled @ K^T : warp rows w*16..+15, cols full 64 ----
        float s[8][4];
        #pragma unroll
        for (int j = 0; j < 8; j++) {
            s[j][0]=s[j][1]=s[j][2]=s[j][3]=0.0f;
            #pragma unroll
            for (int kc = 0; kc < 12; kc++) {
                uint32_t b0 = __float_as_uint(Ks[(j*8+g)*LD + kc*8 + t]);
                uint32_t b1 = __float_as_uint(Ks[(j*8+g)*LD + kc*8 + t + 4]);
                mma8(s[j], qa[kc][0],qa[kc][1],qa[kc][2],qa[kc][3], b0,b1);
            }
        }

        // ---- causal mask (only near diagonal) ----
        if (kt*64 + 63 > rlo) {
            #pragma unroll
            for (int j = 0; j < 8; j++) {
                int c0 = kt*64 + j*8 + 2*t;
                if (c0     > rlo) s[j][0] = -1e30f;
                if (c0 + 1 > rlo) s[j][1] = -1e30f;
                if (c0     > rhi) s[j][2] = -1e30f;
                if (c0 + 1 > rhi) s[j][3] = -1e30f;
            }
        }

        // ---- online softmax in registers ----
        float pm_lo = -1e30f, pm_hi = -1e30f;
        #pragma unroll
        for (int j = 0; j < 8; j++) {
            pm_lo = fmaxf(pm_lo, fmaxf(s[j][0], s[j][1]));
            pm_hi = fmaxf(pm_hi, fmaxf(s[j][2], s[j][3]));
        }
        pm_lo = fmaxf(pm_lo, __shfl_xor_sync(0xffffffffu, pm_lo, 1));
        pm_lo = fmaxf(pm_lo, __shfl_xor_sync(0xffffffffu, pm_lo, 2));
        pm_hi = fmaxf(pm_hi, __shfl_xor_sync(0xffffffffu, pm_hi, 1));
        pm_hi = fmaxf(pm_hi, __shfl_xor_sync(0xffffffffu, pm_hi, 2));

        float mlo_n = fmaxf(m_lo, pm_lo);
        float mhi_n = fmaxf(m_hi, pm_hi);
        float flo = __expf(m_lo - mlo_n);
        float fhi = __expf(m_hi - mhi_n);
        m_lo = mlo_n; m_hi = mhi_n;

        float slo = 0.0f, shi = 0.0f;
        #pragma unroll
        for (int j = 0; j < 8; j++) {
            s[j][0] = __expf(s[j][0] - mlo_n); slo += s[j][0];
            s[j][1] = __expf(s[j][1] - mlo_n); slo += s[j][1];
            s[j][2] = __expf(s[j][2] - mhi_n); shi += s[j][2];
            s[j][3] = __expf(s[j][3] - mhi_n); shi += s[j][3];
        }
        slo += __shfl_xor_sync(0xffffffffu, slo, 1);
        slo += __shfl_xor_sync(0xffffffffu, slo, 2);
        shi += __shfl_xor_sync(0xffffffffu, shi, 1);
        shi += __shfl_xor_sync(0xffffffffu, shi, 2);
        l_lo = l_lo*flo + slo;
        l_hi = l_hi*fhi + shi;

        #pragma unroll
        for (int n = 0; n < 12; n++) {
            o[n][0]*=flo; o[n][1]*=flo; o[n][2]*=fhi; o[n][3]*=fhi;
        }

        // ---- round P to tf32 (rna) before feeding the MMA ----
        #pragma unroll
        for (int j = 0; j < 8; j++) {
            s[j][0] = to_tf32(s[j][0]);
            s[j][1] = to_tf32(s[j][1]);
            s[j][2] = to_tf32(s[j][2]);
            s[j][3] = to_tf32(s[j][3]);
        }

        // ---- O += P @ V : convert P accum->A frags via shfl, then mma ----
        const int src = (g << 2) + (t >> 1);
        #pragma unroll
        for (int j = 0; j < 8; j++) {
            float v0 = __shfl_sync(0xffffffffu, s[j][0], src);
            float v1 = __shfl_sync(0xffffffffu, s[j][1], src);
            float v2 = __shfl_sync(0xffffffffu, s[j][2], src);
            float v3 = __shfl_sync(0xffffffffu, s[j][3], src);
            float u0 = __shfl_sync(0xffffffffu, s[j][0], src + 2);
            float u1 = __shfl_sync(0xffffffffu, s[j][1], src + 2);
            float u2 = __shfl_sync(0xffffffffu, s[j][2], src + 2);
            float u3 = __shfl_sync(0xffffffffu, s[j][3], src + 2);
            bool odd = (t & 1);
            uint32_t pa0 = __float_as_uint(odd ? v1 : v0);  // P[g   ][t  ]
            uint32_t pa1 = __float_as_uint(odd ? v3 : v2);  // P[g+8 ][t  ]
            uint32_t pa2 = __float_as_uint(odd ? u1 : u0);  // P[g   ][t+4]
            uint32_t pa3 = __float_as_uint(odd ? u3 : u2);  // P[g+8 ][t+4]
            #pragma unroll
            for (int n = 0; n < 12; n++) {
                uint32_t b0 = __float_as_uint(Vs[(j*8 + t)*LD + n*8 + g]);
                uint32_t b1 = __float_as_uint(Vs[(j*8 + t + 4)*LD + n*8 + g]);
                mma8(o[n], pa0,pa1,pa2,pa3, b0,b1);
            }
        }
        __syncthreads();
    }

    // ---- normalize and store ----
    const float ilo = 1.0f / l_lo;
    const float ihi = 1.0f / l_hi;
    const int orow = rq0 + w*16 + g;
    #pragma unroll
    for (int n = 0; n < 12; n++) {
        float2 lo = make_float2(o[n][0]*ilo, o[n][1]*ilo);
        float2 hi = make_float2(o[n][2]*ihi, o[n][3]*ihi);
        *reinterpret_cast<float2*>(&out[(size_t)orow*H_ + n*8 + 2*t]) = lo;
        *reinterpret_cast<float2*>(&out[(size_t)(orow+8)*H_ + n*8 + 2*t]) = hi;
    }
}

// ----------------------------- Launch -----------------------------
extern "C" void kernel_launch(void* const* d_in, const int* in_sizes, int n_in,
                              void* d_out, int out_size)
{
    const float* x  = (const float*)d_in[0];
    const float* Wq = (const float*)d_in[1];
    const float* Wk = (const float*)d_in[2];
    const float* Wv = (const float*)d_in[3];
    float* out = (float*)d_out;

    cudaFuncSetAttribute(qkv_kernel, cudaFuncAttributeMaxDynamicSharedMemorySize,
                         QKV_SMEM_BYTES);
    cudaFuncSetAttribute(attn_kernel, cudaFuncAttributeMaxDynamicSharedMemorySize,
                         ATTN_SMEM_BYTES);

    dim3 g1(M_/128, 3);
    qkv_kernel<<<g1, 128, QKV_SMEM_BYTES>>>(x, Wq, Wk, Wv);

    dim3 g2(S_/128, B_);
    attn_kernel<<<g2, 256, ATTN_SMEM_BYTES>>>(out);
}

// round 10
// speedup vs baseline: 3.2177x; 1.1264x over previous
#include <cuda_runtime.h>
#include <cstdint>

#define B_ 16
#define S_ 2048
#define E_ 768
#define H_ 96
#define M_ (B_*S_)

// Scratch: q (pre-scaled, tf32-rounded), k, v (tf32-rounded, row-major)
__device__ float g_q[M_*H_];
__device__ float g_k[M_*H_];
__device__ float g_v[M_*H_];

#define SCALE_ 0.1020620726159658f   // 96^-0.5

__device__ __forceinline__ float to_tf32(float x)
{
    asm("cvt.rna.tf32.f32 %0, %1;" : "=f"(x) : "f"(x));
    return x;
}

__device__ __forceinline__ void mma8(float c[4],
                                     uint32_t a0, uint32_t a1, uint32_t a2, uint32_t a3,
                                     uint32_t b0, uint32_t b1)
{
    asm volatile(
        "mma.sync.aligned.m16n8k8.row.col.f32.tf32.tf32.f32 "
        "{%0,%1,%2,%3}, {%4,%5,%6,%7}, {%8,%9}, {%0,%1,%2,%3};\n"
        : "+f"(c[0]), "+f"(c[1]), "+f"(c[2]), "+f"(c[3])
        : "r"(a0), "r"(a1), "r"(a2), "r"(a3), "r"(b0), "r"(b1));
}

__device__ __forceinline__ void cpa16(uint32_t dst, const float* src)
{
    asm volatile("cp.async.cg.shared.global [%0], [%1], 16;\n" :: "r"(dst), "l"(src) : "memory");
}
__device__ __forceinline__ void cpa_commit() { asm volatile("cp.async.commit_group;\n" ::: "memory"); }
__device__ __forceinline__ void cpa_wait1()  { asm volatile("cp.async.wait_group 1;\n" ::: "memory"); }

// ----------------------------- QKV projection -----------------------------
// EXACT R6 kernel (passing); only the epilogue now rounds (and scales Q).
// C[32768,96] = X @ W. 128 threads = 4 warps, each warp 32 rows x 96 cols.
#define XLD 36
#define WLD 104
#define QKV_SMEM_BYTES ((128*XLD + 32*WLD)*4)

__global__ __launch_bounds__(128) void qkv_kernel(
    const float* __restrict__ X,
    const float* __restrict__ Wq,
    const float* __restrict__ Wk,
    const float* __restrict__ Wv)
{
    extern __shared__ float qs[];
    float* Xs = qs;             // [128][XLD]
    float* Ws = qs + 128*XLD;   // [32][WLD]

    const int tid  = threadIdx.x;
    const int w    = tid >> 5;
    const int lane = tid & 31;
    const int g    = lane >> 2;
    const int t    = lane & 3;
    const int row0 = blockIdx.x * 128;
    const int y    = blockIdx.y;

    const float* W = (y == 0) ? Wq : (y == 1) ? Wk : Wv;
    float* Out     = (y == 0) ? g_q : (y == 1) ? g_k : g_v;
    const float sc = (y == 0) ? SCALE_ : 1.0f;

    float o[2][12][4];
    #pragma unroll
    for (int r = 0; r < 2; r++)
        #pragma unroll
        for (int n = 0; n < 12; n++)
            o[r][n][0] = o[r][n][1] = o[r][n][2] = o[r][n][3] = 0.0f;

    for (int kt = 0; kt < E_/32; kt++) {
        // X tile 128x32 = 1024 float4, 8 per thread
        #pragma unroll
        for (int i = 0; i < 8; i++) {
            int idx = tid + i*128;
            int r = idx >> 3, c4 = idx & 7;
            float4 v = *reinterpret_cast<const float4*>(
                &X[(size_t)(row0 + r)*E_ + kt*32 + c4*4]);
            float* d = &Xs[r*XLD + c4*4];
            d[0]=to_tf32(v.x); d[1]=to_tf32(v.y); d[2]=to_tf32(v.z); d[3]=to_tf32(v.w);
        }
        // W tile 32x96 = 768 float4, 6 per thread
        #pragma unroll
        for (int i = 0; i < 6; i++) {
            int idx = tid + i*128;
            int r = idx / 24, c4 = idx - r*24;
            float4 v = *reinterpret_cast<const float4*>(
                &W[(size_t)(kt*32 + r)*H_ + c4*4]);
            float* d = &Ws[r*WLD + c4*4];
            d[0]=to_tf32(v.x); d[1]=to_tf32(v.y); d[2]=to_tf32(v.z); d[3]=to_tf32(v.w);
        }
        __syncthreads();

        #pragma unroll
        for (int kc = 0; kc < 4; kc++) {
            uint32_t a[2][4];
            #pragma unroll
            for (int rt = 0; rt < 2; rt++) {
                int rr = w*32 + rt*16 + g;
                a[rt][0] = __float_as_uint(Xs[rr*XLD + kc*8 + t]);
                a[rt][1] = __float_as_uint(Xs[(rr+8)*XLD + kc*8 + t]);
                a[rt][2] = __float_as_uint(Xs[rr*XLD + kc*8 + t + 4]);
                a[rt][3] = __float_as_uint(Xs[(rr+8)*XLD + kc*8 + t + 4]);
            }
            #pragma unroll
            for (int n = 0; n < 12; n++) {
                uint32_t b0 = __float_as_uint(Ws[(kc*8 + t)*WLD + n*8 + g]);
                uint32_t b1 = __float_as_uint(Ws[(kc*8 + t + 4)*WLD + n*8 + g]);
                mma8(o[0][n], a[0][0],a[0][1],a[0][2],a[0][3], b0,b1);
                mma8(o[1][n], a[1][0],a[1][1],a[1][2],a[1][3], b0,b1);
            }
        }
        __syncthreads();
    }

    // epilogue: tf32-round (Q also pre-scaled) so attn can consume directly
    #pragma unroll
    for (int rt = 0; rt < 2; rt++) {
        int rr = row0 + w*32 + rt*16 + g;
        #pragma unroll
        for (int n = 0; n < 12; n++) {
            float2 lo = make_float2(to_tf32(o[rt][n][0]*sc), to_tf32(o[rt][n][1]*sc));
            float2 hi = make_float2(to_tf32(o[rt][n][2]*sc), to_tf32(o[rt][n][3]*sc));
            *reinterpret_cast<float2*>(&Out[(size_t)rr*H_ + n*8 + 2*t]) = lo;
            *reinterpret_cast<float2*>(&Out[(size_t)(rr+8)*H_ + n*8 + 2*t]) = hi;
        }
    }
}

// ----------------------------- Attention -----------------------------
// R6 body. Deltas: Q frags direct from gmem (pre-scaled/rounded), K/V via
// cp.async double-buffer (2 barriers/tile, same skeleton as R6), KLD=100
// (conflict-free K frags; V at 104 was already conflict-free).
#define KLD 100
#define VLD 104
#define STAGEF (64*KLD + 64*VLD)          // 13056 floats
#define ATTN_SMEM_BYTES (2*STAGEF*4)      // 104448 B

__device__ __forceinline__ void attn_fill(int b, int kt, uint32_t st_u, int tid)
{
    uint32_t ks_u = st_u;
    uint32_t vs_u = st_u + (uint32_t)(64*KLD)*4;
    #pragma unroll
    for (int i = 0; i < 6; i++) {           // 64 rows x 24 float4 = 1536
        int idx = tid + i*256;
        int r = idx / 24, c = idx - r*24;
        size_t gb = (size_t)(b*S_ + kt*64 + r)*H_ + c*4;
        cpa16(ks_u + (uint32_t)(r*KLD + c*4)*4, &g_k[gb]);
        cpa16(vs_u + (uint32_t)(r*VLD + c*4)*4, &g_v[gb]);
    }
}

__global__ __launch_bounds__(256) void attn_kernel(float* __restrict__ out)
{
    extern __shared__ float smem[];
    const int tid  = threadIdx.x;
    const int w    = tid >> 5;
    const int lane = tid & 31;
    const int g    = lane >> 2;
    const int t    = lane & 3;
    const int qt   = (S_/128 - 1) - blockIdx.x;   // big CTAs first
    const int b    = blockIdx.y;
    const int rq0  = b*S_ + qt*128;

    const uint32_t smem_u = (uint32_t)__cvta_generic_to_shared(smem);

    // Q fragments straight from gmem (pre-scaled, pre-rounded, L2-resident)
    uint32_t qa[12][4];
    {
        const size_t qr0 = (size_t)(rq0 + w*16 + g)*H_;
        const size_t qr8 = qr0 + 8*H_;
        #pragma unroll
        for (int kc = 0; kc < 12; kc++) {
            qa[kc][0] = __float_as_uint(g_q[qr0 + kc*8 + t]);
            qa[kc][1] = __float_as_uint(g_q[qr8 + kc*8 + t]);
            qa[kc][2] = __float_as_uint(g_q[qr0 + kc*8 + t + 4]);
            qa[kc][3] = __float_as_uint(g_q[qr8 + kc*8 + t + 4]);
        }
    }

    float o[12][4];
    #pragma unroll
    for (int n = 0; n < 12; n++)
        o[n][0] = o[n][1] = o[n][2] = o[n][3] = 0.0f;

    float m_lo = -1e30f, m_hi = -1e30f, l_lo = 0.0f, l_hi = 0.0f;
    const int rlo = qt*128 + w*16 + g;
    const int rhi = rlo + 8;
    const int nkt = 2*qt + 2;

    // prologue: prefetch tile 0
    attn_fill(b, 0, smem_u, tid);
    cpa_commit();

    for (int kt = 0; kt < nkt; kt++) {
        // issue next tile, then wait for current (all but newest group)
        if (kt + 1 < nkt)
            attn_fill(b, kt + 1, smem_u + (uint32_t)(((kt+1)&1)*STAGEF)*4, tid);
        cpa_commit();
        cpa_wait1();
        __syncthreads();

        const float* Ks = smem + (kt & 1)*STAGEF;
        const float* Vs = Ks + 64*KLD;

        // ---- S = Qscaled @ K^T ----
        float s[8][4];
        #pragma unroll
        for (int j = 0; j < 8; j++) {
            s[j][0]=s[j][1]=s[j][2]=s[j][3]=0.0f;
            #pragma unroll
            for (int kc = 0; kc < 12; kc++) {
                uint32_t b0 = __float_as_uint(Ks[(j*8+g)*KLD + kc*8 + t]);
                uint32_t b1 = __float_as_uint(Ks[(j*8+g)*KLD + kc*8 + t + 4]);
                mma8(s[j], qa[kc][0],qa[kc][1],qa[kc][2],qa[kc][3], b0,b1);
            }
        }

        // ---- causal mask (near diagonal only) ----
        if (kt*64 + 63 > rlo) {
            #pragma unroll
            for (int j = 0; j < 8; j++) {
                int c0 = kt*64 + j*8 + 2*t;
                if (c0     > rlo) s[j][0] = -1e30f;
                if (c0 + 1 > rlo) s[j][1] = -1e30f;
                if (c0     > rhi) s[j][2] = -1e30f;
                if (c0 + 1 > rhi) s[j][3] = -1e30f;
            }
        }

        // ---- online softmax in registers ----
        float pm_lo = -1e30f, pm_hi = -1e30f;
        #pragma unroll
        for (int j = 0; j < 8; j++) {
            pm_lo = fmaxf(pm_lo, fmaxf(s[j][0], s[j][1]));
            pm_hi = fmaxf(pm_hi, fmaxf(s[j][2], s[j][3]));
        }
        pm_lo = fmaxf(pm_lo, __shfl_xor_sync(0xffffffffu, pm_lo, 1));
        pm_lo = fmaxf(pm_lo, __shfl_xor_sync(0xffffffffu, pm_lo, 2));
        pm_hi = fmaxf(pm_hi, __shfl_xor_sync(0xffffffffu, pm_hi, 1));
        pm_hi = fmaxf(pm_hi, __shfl_xor_sync(0xffffffffu, pm_hi, 2));

        float mlo_n = fmaxf(m_lo, pm_lo);
        float mhi_n = fmaxf(m_hi, pm_hi);
        float flo = __expf(m_lo - mlo_n);
        float fhi = __expf(m_hi - mhi_n);
        m_lo = mlo_n; m_hi = mhi_n;

        float slo = 0.0f, shi = 0.0f;
        #pragma unroll
        for (int j = 0; j < 8; j++) {
            s[j][0] = __expf(s[j][0] - mlo_n); slo += s[j][0];
            s[j][1] = __expf(s[j][1] - mlo_n); slo += s[j][1];
            s[j][2] = __expf(s[j][2] - mhi_n); shi += s[j][2];
            s[j][3] = __expf(s[j][3] - mhi_n); shi += s[j][3];
        }
        slo += __shfl_xor_sync(0xffffffffu, slo, 1);
        slo += __shfl_xor_sync(0xffffffffu, slo, 2);
        shi += __shfl_xor_sync(0xffffffffu, shi, 1);
        shi += __shfl_xor_sync(0xffffffffu, shi, 2);
        l_lo = l_lo*flo + slo;
        l_hi = l_hi*fhi + shi;

        #pragma unroll
        for (int n = 0; n < 12; n++) {
            o[n][0]*=flo; o[n][1]*=flo; o[n][2]*=fhi; o[n][3]*=fhi;
        }

        // ---- round P to tf32 (rna) ----
        #pragma unroll
        for (int j = 0; j < 8; j++) {
            s[j][0] = to_tf32(s[j][0]);
            s[j][1] = to_tf32(s[j][1]);
            s[j][2] = to_tf32(s[j][2]);
            s[j][3] = to_tf32(s[j][3]);
        }

        // ---- O += P @ V : P accum->A frags via shfl ----
        const int src = (g << 2) + (t >> 1);
        #pragma unroll
        for (int j = 0; j < 8; j++) {
            float v0 = __shfl_sync(0xffffffffu, s[j][0], src);
            float v1 = __shfl_sync(0xffffffffu, s[j][1], src);
            float v2 = __shfl_sync(0xffffffffu, s[j][2], src);
            float v3 = __shfl_sync(0xffffffffu, s[j][3], src);
            float u0 = __shfl_sync(0xffffffffu, s[j][0], src + 2);
            float u1 = __shfl_sync(0xffffffffu, s[j][1], src + 2);
            float u2 = __shfl_sync(0xffffffffu, s[j][2], src + 2);
            float u3 = __shfl_sync(0xffffffffu, s[j][3], src + 2);
            bool odd = (t & 1);
            uint32_t pa0 = __float_as_uint(odd ? v1 : v0);
            uint32_t pa1 = __float_as_uint(odd ? v3 : v2);
            uint32_t pa2 = __float_as_uint(odd ? u1 : u0);
            uint32_t pa3 = __float_as_uint(odd ? u3 : u2);
            #pragma unroll
            for (int n = 0; n < 12; n++) {
                uint32_t b0 = __float_as_uint(Vs[(j*8 + t)*VLD + n*8 + g]);
                uint32_t b1 = __float_as_uint(Vs[(j*8 + t + 4)*VLD + n*8 + g]);
                mma8(o[n], pa0,pa1,pa2,pa3, b0,b1);
            }
        }
        __syncthreads();   // all reads of this buffer done before next fill overwrites it
    }

    // ---- normalize and store ----
    const float ilo = 1.0f / l_lo;
    const float ihi = 1.0f / l_hi;
    const int orow = rq0 + w*16 + g;
    #pragma unroll
    for (int n = 0; n < 12; n++) {
        float2 lo = make_float2(o[n][0]*ilo, o[n][1]*ilo);
        float2 hi = make_float2(o[n][2]*ihi, o[n][3]*ihi);
        *reinterpret_cast<float2*>(&out[(size_t)orow*H_ + n*8 + 2*t]) = lo;
        *reinterpret_cast<float2*>(&out[(size_t)(orow+8)*H_ + n*8 + 2*t]) = hi;
    }
}

// ----------------------------- Launch -----------------------------
extern "C" void kernel_launch(void* const* d_in, const int* in_sizes, int n_in,
                              void* d_out, int out_size)
{
    const float* x  = (const float*)d_in[0];
    const float* Wq = (const float*)d_in[1];
    const float* Wk = (const float*)d_in[2];
    const float* Wv = (const float*)d_in[3];
    float* out = (float*)d_out;

    cudaFuncSetAttribute(qkv_kernel, cudaFuncAttributeMaxDynamicSharedMemorySize,
                         QKV_SMEM_BYTES);
    cudaFuncSetAttribute(attn_kernel, cudaFuncAttributeMaxDynamicSharedMemorySize,
                         ATTN_SMEM_BYTES);

    dim3 g1(M_/128, 3);
    qkv_kernel<<<g1, 128, QKV_SMEM_BYTES>>>(x, Wq, Wk, Wv);

    dim3 g2(S_/128, B_);
    attn_kernel<<<g2, 256, ATTN_SMEM_BYTES>>>(out);
}